// round 2
// baseline (speedup 1.0000x reference)
#include <cuda_runtime.h>
#include <math.h>

#define B_  4
#define T_  2048
#define C_  1024
#define NH_ 16
#define HD_ 64
#define M_  (B_*T_)   // 8192 rows

// ---- scratch (static __device__ arrays: allocation-free) ----
static __device__ float g_q[B_*NH_*T_*HD_];    // [b][h][t][d]
static __device__ float g_k[B_*NH_*T_*HD_];
static __device__ float g_v[B_*NH_*T_*HD_];
static __device__ float g_att[M_*C_];          // [b][t][h*64+d]
static __device__ float g_cos[T_*32];
static __device__ float g_sin[T_*32];

// ============================================================
// RoPE tables (fp64 once -> fp32 tables)
// ============================================================
__global__ void rope_table_kernel()
{
    int idx = blockIdx.x * blockDim.x + threadIdx.x;
    if (idx >= T_ * 32) return;
    int t = idx >> 5, i = idx & 31;
    double inv = pow(10000.0, -(double)i / 32.0);
    double ang = (double)t * inv;
    g_cos[idx] = (float)cos(ang);
    g_sin[idx] = (float)sin(ang);
}

// ============================================================
// RoPE apply (in-place on g_q / g_k, selected by blockIdx.y)
// ============================================================
__global__ void rope_apply_kernel()
{
    int idx = blockIdx.x * blockDim.x + threadIdx.x;
    const int total = B_ * NH_ * T_ * 32;
    if (idx >= total) return;
    float* buf = (blockIdx.y == 0) ? g_q : g_k;
    int i   = idx & 31;
    int bht = idx >> 5;
    int t   = bht & (T_ - 1);
    float c = g_cos[t * 32 + i];
    float s = g_sin[t * 32 + i];
    float* base = buf + bht * HD_;
    float x1 = base[i], x2 = base[i + 32];
    base[i]      = x1 * c - x2 * s;
    base[i + 32] = x1 * s + x2 * c;
}

// ============================================================
// SGEMM: C[M,N] = A[M,1024] @ W[1024,N] + bias
//   128x128x16 tiles, 256 threads, 8x8 micro-tile (4+4 split).
//   MODE 0: N=3072, scatter into g_q/g_k/g_v as [b][h][t][d]
//   MODE 1: N=1024, A := g_att, write to `out`
// ============================================================
template<int N, int MODE>
__global__ __launch_bounds__(256)
void sgemm_kernel(const float* __restrict__ A, const float* __restrict__ W,
                  const float* __restrict__ bias, float* __restrict__ out)
{
    __shared__ float As[16 * 128];
    __shared__ float Bs[16 * 128];
    const int bm = blockIdx.y, bn = blockIdx.x;
    const int tid = threadIdx.x;
    const int tx = tid & 15, ty = tid >> 4;

    const float* Asrc = (MODE == 0) ? A : g_att;
    const float* Ag = Asrc + bm * 128 * C_;
    const float* Wg = W + bn * 128;

    float acc[8][8];
#pragma unroll
    for (int i = 0; i < 8; i++)
#pragma unroll
        for (int j = 0; j < 8; j++) acc[i][j] = 0.f;

    for (int k0 = 0; k0 < C_; k0 += 16) {
        // A tile 128x16, stored transposed As[k][m]
#pragma unroll
        for (int i = 0; i < 2; i++) {
            int p = tid + i * 256;          // 0..511 float4 slots
            int row = p >> 2;
            int c4  = (p & 3) * 4;
            float4 v = *(const float4*)(Ag + row * C_ + k0 + c4);
            As[(c4 + 0) * 128 + row] = v.x;
            As[(c4 + 1) * 128 + row] = v.y;
            As[(c4 + 2) * 128 + row] = v.z;
            As[(c4 + 3) * 128 + row] = v.w;
        }
        // B tile 16x128, Bs[k][n]
#pragma unroll
        for (int i = 0; i < 2; i++) {
            int p = tid + i * 256;
            int row = p >> 5;
            int c4  = (p & 31) * 4;
            *(float4*)(Bs + row * 128 + c4) =
                *(const float4*)(Wg + (k0 + row) * N + c4);
        }
        __syncthreads();
#pragma unroll
        for (int kk = 0; kk < 16; kk++) {
            float a[8], b[8];
            *(float4*)(a)     = *(const float4*)(As + kk * 128 + ty * 4);
            *(float4*)(a + 4) = *(const float4*)(As + kk * 128 + 64 + ty * 4);
            *(float4*)(b)     = *(const float4*)(Bs + kk * 128 + tx * 4);
            *(float4*)(b + 4) = *(const float4*)(Bs + kk * 128 + 64 + tx * 4);
#pragma unroll
            for (int i = 0; i < 8; i++)
#pragma unroll
                for (int j = 0; j < 8; j++)
                    acc[i][j] += a[i] * b[j];
        }
        __syncthreads();
    }

    // epilogue
#pragma unroll
    for (int i = 0; i < 8; i++) {
        int m = bm * 128 + ((i < 4) ? (ty * 4 + i) : (64 + ty * 4 + (i - 4)));
#pragma unroll
        for (int jj = 0; jj < 2; jj++) {
            int n0 = bn * 128 + ((jj == 0) ? (tx * 4) : (64 + tx * 4));
            float4 r;
            r.x = acc[i][jj * 4 + 0] + bias[n0 + 0];
            r.y = acc[i][jj * 4 + 1] + bias[n0 + 1];
            r.z = acc[i][jj * 4 + 2] + bias[n0 + 2];
            r.w = acc[i][jj * 4 + 3] + bias[n0 + 3];
            if (MODE == 0) {
                int sec = n0 >> 10;           // 0=q 1=k 2=v
                int w   = n0 & 1023;
                int h = w >> 6, d = w & 63;   // d aligned to 4
                int bb = m / T_, t = m & (T_ - 1);
                float* dst = (sec == 0) ? g_q : (sec == 1) ? g_k : g_v;
                *(float4*)(dst + (((bb * NH_ + h) * T_ + t) * HD_ + d)) = r;
            } else {
                *(float4*)(out + m * N + n0) = r;
            }
        }
    }
}

// ============================================================
// Fused causal flash attention (fp32, online softmax)
//   grid (T/128, B*H), 128 threads; one query row per thread.
//   K/V tiles 32x64 in smem (broadcast reads), scores in regs.
// ============================================================
__global__ __launch_bounds__(128)
void attn_kernel()
{
    __shared__ float Ks[32 * 64];
    __shared__ float Vs[32 * 64];

    const int bh  = blockIdx.y;
    const int qt  = gridDim.x - 1 - blockIdx.x;   // heavy tiles first
    const int q0  = qt * 128;
    const int tid = threadIdx.x;
    const int qi  = q0 + tid;

    const float* Q = g_q + bh * T_ * HD_;
    const float* K = g_k + bh * T_ * HD_;
    const float* V = g_v + bh * T_ * HD_;

    const float scale = 0.125f;   // 1/sqrt(64)
    float q[64];
#pragma unroll
    for (int d = 0; d < 64; d += 4) {
        float4 v4 = *(const float4*)(Q + qi * 64 + d);
        q[d] = v4.x * scale; q[d + 1] = v4.y * scale;
        q[d + 2] = v4.z * scale; q[d + 3] = v4.w * scale;
    }

    float acc[64];
#pragma unroll
    for (int d = 0; d < 64; d++) acc[d] = 0.f;
    float m = -INFINITY, l = 0.f;

    const int kend = q0 + 128;
    for (int k0 = 0; k0 < kend; k0 += 32) {
        // load K,V tile 32x64 (512 float4 each)
#pragma unroll
        for (int i = 0; i < 4; i++) {
            int p  = tid + i * 128;
            int r  = p >> 4;
            int c4 = (p & 15) * 4;
            *(float4*)(Ks + r * 64 + c4) = *(const float4*)(K + (k0 + r) * 64 + c4);
            *(float4*)(Vs + r * 64 + c4) = *(const float4*)(V + (k0 + r) * 64 + c4);
        }
        __syncthreads();

        float s[32];
        float tmax = -INFINITY;
#pragma unroll
        for (int j = 0; j < 32; j++) {
            float sum = 0.f;
#pragma unroll
            for (int d = 0; d < 64; d += 4) {
                float4 kv = *(const float4*)(Ks + j * 64 + d);
                sum += q[d] * kv.x + q[d + 1] * kv.y
                     + q[d + 2] * kv.z + q[d + 3] * kv.w;
            }
            s[j] = ((k0 + j) <= qi) ? sum : -INFINITY;
            tmax = fmaxf(tmax, s[j]);
        }

        float mnew  = fmaxf(m, tmax);
        float alpha = expf(m - mnew);   // 0 on first tile (m=-inf)
        m = mnew;
        l *= alpha;
#pragma unroll
        for (int d = 0; d < 64; d++) acc[d] *= alpha;

#pragma unroll
        for (int j = 0; j < 32; j++) {
            float p = expf(s[j] - mnew);   // exact 0 for masked keys
            l += p;
#pragma unroll
            for (int d = 0; d < 64; d += 4) {
                float4 vv = *(const float4*)(Vs + j * 64 + d);
                acc[d]     += p * vv.x;
                acc[d + 1] += p * vv.y;
                acc[d + 2] += p * vv.z;
                acc[d + 3] += p * vv.w;
            }
        }
        __syncthreads();
    }

    // write out as [b][t][h*64+d] for the proj GEMM
    const int b = bh / NH_, h = bh & (NH_ - 1);
    const float inv_l = 1.f / l;
    float* outp = g_att + ((b * T_ + qi) * NH_ + h) * HD_;
#pragma unroll
    for (int d = 0; d < 64; d += 4) {
        float4 o;
        o.x = acc[d] * inv_l;     o.y = acc[d + 1] * inv_l;
        o.z = acc[d + 2] * inv_l; o.w = acc[d + 3] * inv_l;
        *(float4*)(outp + d) = o;
    }
}

// ============================================================
// launcher
// ============================================================
extern "C" void kernel_launch(void* const* d_in, const int* in_sizes, int n_in,
                              void* d_out, int out_size)
{
    (void)in_sizes; (void)n_in;
    const float* x     = (const float*)d_in[0];
    const float* rnn   = (const float*)d_in[1];
    const float* Wqkv  = (const float*)d_in[2];
    const float* bqkv  = (const float*)d_in[3];
    const float* Wproj = (const float*)d_in[4];
    const float* bproj = (const float*)d_in[5];
    float* out = (float*)d_out;

    rope_table_kernel<<<(T_ * 32 + 255) / 256, 256>>>();

    sgemm_kernel<3 * C_, 0><<<dim3(24, 64), 256>>>(x, Wqkv, bqkv, nullptr);

    dim3 rg((B_ * NH_ * T_ * 32 + 255) / 256, 2);
    rope_apply_kernel<<<rg, 256>>>();

    attn_kernel<<<dim3(T_ / 128, B_ * NH_), 128>>>();

    sgemm_kernel<C_, 1><<<dim3(8, 64), 256>>>(nullptr, Wproj, bproj, out);

    // rnn_state passthrough -> tail of output buffer
    if (out_size >= (int)(M_ * C_ + B_ * C_)) {
        cudaMemcpyAsync(out + (size_t)M_ * C_, rnn,
                        (size_t)B_ * C_ * sizeof(float),
                        cudaMemcpyDeviceToDevice);
    }
}

// round 5
// speedup vs baseline: 1.3056x; 1.3056x over previous
#include <cuda_runtime.h>
#include <cuda_bf16.h>
#include <cstdint>
#include <math.h>

#define B_  4
#define T_  2048
#define C_  1024
#define NH_ 16
#define HD_ 64
#define M_  (B_*T_)   // 8192 rows

// ---- scratch (static __device__ arrays: allocation-free) ----
static __device__ float g_q[B_*NH_*T_*HD_];    // [b][h][t][d]
static __device__ float g_k[B_*NH_*T_*HD_];
static __device__ float g_v[B_*NH_*T_*HD_];
static __device__ float g_cos[T_*32];
static __device__ float g_sin[T_*32];
static __device__ __nv_bfloat16 g_ahi[M_*C_];    // x split hi  [m][k]
static __device__ __nv_bfloat16 g_alo[M_*C_];    // x split lo
static __device__ __nv_bfloat16 g_atthi[M_*C_];  // attn out split hi [m][h*64+d]
static __device__ __nv_bfloat16 g_attlo[M_*C_];
static __device__ __nv_bfloat16 g_bhi[3*C_*C_];  // W transposed [N][K] hi
static __device__ __nv_bfloat16 g_blo[3*C_*C_];  // W transposed [N][K] lo

// ============================================================
// helpers (baseline PTX only: works on generic compute_103)
// ============================================================
__device__ __forceinline__ uint32_t smem_u32(const void* p) {
    uint32_t a;
    asm("{ .reg .u64 t; cvta.to.shared.u64 t, %1; cvt.u32.u64 %0, t; }"
        : "=r"(a) : "l"(p));
    return a;
}
__device__ __forceinline__ void cpasync16(uint32_t dst, const void* src) {
    asm volatile("cp.async.ca.shared.global [%0], [%1], 16;"
                 :: "r"(dst), "l"(__cvta_generic_to_global(src)));
}
#define CP_COMMIT() asm volatile("cp.async.commit_group;" ::: "memory")
#define CP_WAIT1()  asm volatile("cp.async.wait_group 1;" ::: "memory")
#define CP_WAIT0()  asm volatile("cp.async.wait_group 0;" ::: "memory")

__device__ __forceinline__ void ldsm4(uint32_t* r, uint32_t addr) {
    asm volatile("ldmatrix.sync.aligned.m8n8.x4.shared.b16 {%0,%1,%2,%3}, [%4];"
                 : "=r"(r[0]), "=r"(r[1]), "=r"(r[2]), "=r"(r[3]) : "r"(addr));
}
__device__ __forceinline__ void ldsm2(uint32_t* r, uint32_t addr) {
    asm volatile("ldmatrix.sync.aligned.m8n8.x2.shared.b16 {%0,%1}, [%2];"
                 : "=r"(r[0]), "=r"(r[1]) : "r"(addr));
}
__device__ __forceinline__ void mma_bf16(float* c, const uint32_t* a, const uint32_t* b) {
    asm volatile("mma.sync.aligned.m16n8k16.row.col.f32.bf16.bf16.f32 "
                 "{%0,%1,%2,%3}, {%4,%5,%6,%7}, {%8,%9}, {%0,%1,%2,%3};"
                 : "+f"(c[0]), "+f"(c[1]), "+f"(c[2]), "+f"(c[3])
                 : "r"(a[0]), "r"(a[1]), "r"(a[2]), "r"(a[3]),
                   "r"(b[0]), "r"(b[1]));
}
__device__ __forceinline__ uint32_t pk2(__nv_bfloat16 a, __nv_bfloat16 b) {
    __nv_bfloat162 t; t.x = a; t.y = b;
    return *reinterpret_cast<uint32_t*>(&t);
}

// ============================================================
// RoPE tables (fp64 once -> fp32 tables)
// ============================================================
__global__ void rope_table_kernel()
{
    int idx = blockIdx.x * blockDim.x + threadIdx.x;
    if (idx >= T_ * 32) return;
    int t = idx >> 5, i = idx & 31;
    double inv = pow(10000.0, -(double)i / 32.0);
    double ang = (double)t * inv;
    g_cos[idx] = (float)cos(ang);
    g_sin[idx] = (float)sin(ang);
}

// ============================================================
// RoPE apply (in-place on g_q / g_k)
// ============================================================
__global__ void rope_apply_kernel()
{
    int idx = blockIdx.x * blockDim.x + threadIdx.x;
    const int total = B_ * NH_ * T_ * 32;
    if (idx >= total) return;
    float* buf = (blockIdx.y == 0) ? g_q : g_k;
    int i   = idx & 31;
    int bht = idx >> 5;
    int t   = bht & (T_ - 1);
    float c = g_cos[t * 32 + i];
    float s = g_sin[t * 32 + i];
    float* base = buf + bht * HD_;
    float x1 = base[i], x2 = base[i + 32];
    base[i]      = x1 * c - x2 * s;
    base[i + 32] = x1 * s + x2 * c;
}

// ============================================================
// x -> bf16 hi/lo split (row-major [m][k])
// ============================================================
__global__ __launch_bounds__(256)
void xconv_kernel(const float* __restrict__ x)
{
    int idx = blockIdx.x * 256 + threadIdx.x;   // over M_*C_/4
    float4 v = reinterpret_cast<const float4*>(x)[idx];
    __nv_bfloat16 h0 = __float2bfloat16(v.x);
    __nv_bfloat16 h1 = __float2bfloat16(v.y);
    __nv_bfloat16 h2 = __float2bfloat16(v.z);
    __nv_bfloat16 h3 = __float2bfloat16(v.w);
    uint2 hi = make_uint2(pk2(h0, h1), pk2(h2, h3));
    uint2 lo = make_uint2(
        pk2(__float2bfloat16(v.x - __bfloat162float(h0)),
            __float2bfloat16(v.y - __bfloat162float(h1))),
        pk2(__float2bfloat16(v.z - __bfloat162float(h2)),
            __float2bfloat16(v.w - __bfloat162float(h3))));
    reinterpret_cast<uint2*>(g_ahi)[idx] = hi;
    reinterpret_cast<uint2*>(g_alo)[idx] = lo;
}

// ============================================================
// W transpose + bf16 hi/lo split: g_b{hi,lo}[n][k] = split(W[k][n])
// ============================================================
__global__ __launch_bounds__(256)
void wconv_kernel(const float* __restrict__ W, int N)
{
    __shared__ float s[32][33];
    const int kb = blockIdx.y * 32, nb = blockIdx.x * 32;
    const int tx = threadIdx.x, ty = threadIdx.y;   // 32 x 8
#pragma unroll
    for (int j = 0; j < 4; j++)
        s[ty * 4 + j][tx] = W[(kb + ty * 4 + j) * N + nb + tx];
    __syncthreads();
#pragma unroll
    for (int j = 0; j < 4; j++) {
        float v = s[tx][ty * 4 + j];
        __nv_bfloat16 h = __float2bfloat16(v);
        float lo = v - __bfloat162float(h);
        int idx = (nb + ty * 4 + j) * C_ + kb + tx;
        g_bhi[idx] = h;
        g_blo[idx] = __float2bfloat16(lo);
    }
}

// ============================================================
// bf16 mma.sync GEMM: D[M,N] = A[M,1024] @ Wt[N,1024]^T + bias
//   128x128 block tile, 8 warps (2x4), warp tile 64x32, BK=64,
//   cp.async double-buffered, 3-product hi/lo split.
//   MODE 0: A = g_ahi/lo, scatter into g_q/g_k/g_v
//   MODE 1: A = g_atthi/lo, write fp32 out
// ============================================================
static constexpr int RSB    = 144;          // padded row stride bytes (64 bf16 + 8 pad)
static constexpr int SA_HI  = 0;
static constexpr int SA_LO  = 18432;
static constexpr int SB_HI  = 36864;
static constexpr int SB_LO  = 55296;
static constexpr int STAGE  = 73728;
static constexpr int SMEM_SZ = 2 * STAGE;   // 147456

template<int N, int MODE>
__global__ __launch_bounds__(256)
void mma_gemm_kernel(const float* __restrict__ bias, float* __restrict__ out)
{
    extern __shared__ __align__(128) char smem[];
    const uint32_t sb = smem_u32(smem);
    const int tid = threadIdx.x, lane = tid & 31, wid = tid >> 5;
    const int wm = wid >> 2, wn = wid & 3;
    const int m0 = blockIdx.y * 128, n0 = blockIdx.x * 128;

    const __nv_bfloat16* Ah = (MODE == 0) ? g_ahi : g_atthi;
    const __nv_bfloat16* Al = (MODE == 0) ? g_alo : g_attlo;

    float acc[4][4][4];
#pragma unroll
    for (int a = 0; a < 4; a++)
#pragma unroll
        for (int b = 0; b < 4; b++)
#pragma unroll
            for (int c = 0; c < 4; c++) acc[a][b][c] = 0.f;

    auto prefetch = [&](int chunk) {
        const int st = chunk & 1;
        const int k0 = chunk * 64;
        const uint32_t sbase = sb + st * STAGE;
#pragma unroll
        for (int i = 0; i < 8; i++) {
            int p = tid + i * 256;                 // 0..2047
            int sel = p >> 10, q = p & 1023;
            int row = q >> 3, ch = q & 7;
            const __nv_bfloat16* src =
                (sel ? Al : Ah) + (size_t)(m0 + row) * C_ + k0 + ch * 8;
            cpasync16(sbase + (sel ? SA_LO : SA_HI) + row * RSB + ch * 16, src);
        }
#pragma unroll
        for (int i = 0; i < 8; i++) {
            int p = tid + i * 256;
            int sel = p >> 10, q = p & 1023;
            int row = q >> 3, ch = q & 7;
            const __nv_bfloat16* src =
                (sel ? g_blo : g_bhi) + (size_t)(n0 + row) * C_ + k0 + ch * 8;
            cpasync16(sbase + (sel ? SB_LO : SB_HI) + row * RSB + ch * 16, src);
        }
        CP_COMMIT();
    };

    prefetch(0);

    const int a_r = lane & 15;
    const int a_c = (lane >> 4) * 8;
    const int b_r = lane & 7;
    const int b_c = ((lane >> 3) & 1) * 8;

    for (int chunk = 0; chunk < 16; chunk++) {
        if (chunk + 1 < 16) { prefetch(chunk + 1); CP_WAIT1(); }
        else                { CP_WAIT0(); }
        __syncthreads();
        const uint32_t sbase = sb + (chunk & 1) * STAGE;
#pragma unroll
        for (int ks = 0; ks < 4; ks++) {
            uint32_t fAh[4][4], fAl[4][4], fBh[4][2], fBl[4][2];
#pragma unroll
            for (int mi = 0; mi < 4; mi++) {
                uint32_t off = (uint32_t)((wm * 64 + mi * 16 + a_r) * RSB
                                          + (ks * 16 + a_c) * 2);
                ldsm4(fAh[mi], sbase + SA_HI + off);
                ldsm4(fAl[mi], sbase + SA_LO + off);
            }
#pragma unroll
            for (int ni = 0; ni < 4; ni++) {
                uint32_t off = (uint32_t)((wn * 32 + ni * 8 + b_r) * RSB
                                          + (ks * 16 + b_c) * 2);
                ldsm2(fBh[ni], sbase + SB_HI + off);
                ldsm2(fBl[ni], sbase + SB_LO + off);
            }
#pragma unroll
            for (int mi = 0; mi < 4; mi++)
#pragma unroll
                for (int ni = 0; ni < 4; ni++) {
                    mma_bf16(acc[mi][ni], fAh[mi], fBh[ni]);
                    mma_bf16(acc[mi][ni], fAh[mi], fBl[ni]);
                    mma_bf16(acc[mi][ni], fAl[mi], fBh[ni]);
                }
        }
        __syncthreads();
    }

    // ---- epilogue ----
    const int g = lane >> 2, j = lane & 3;
#pragma unroll
    for (int mi = 0; mi < 4; mi++)
#pragma unroll
        for (int ni = 0; ni < 4; ni++)
#pragma unroll
            for (int half = 0; half < 2; half++) {
                int m = m0 + wm * 64 + mi * 16 + g + half * 8;
                int n = n0 + wn * 32 + ni * 8 + 2 * j;
                float v0 = acc[mi][ni][half * 2 + 0] + bias[n];
                float v1 = acc[mi][ni][half * 2 + 1] + bias[n + 1];
                if (MODE == 0) {
                    int sec = n >> 10;          // 0=q 1=k 2=v
                    int w   = n & 1023;
                    int h = w >> 6, d = w & 63;
                    int bb = m >> 11, t = m & (T_ - 1);
                    float* dst = (sec == 0) ? g_q : (sec == 1) ? g_k : g_v;
                    *(float2*)(dst + (((size_t)(bb * NH_ + h) * T_ + t) * HD_ + d))
                        = make_float2(v0, v1);
                } else {
                    *(float2*)(out + (size_t)m * C_ + n) = make_float2(v0, v1);
                }
            }
}

// ============================================================
// Fused causal flash attention (fp32, online softmax)
//   writes bf16 hi/lo split output for the proj GEMM
// ============================================================
__global__ __launch_bounds__(128)
void attn_kernel()
{
    __shared__ float Ks[32 * 64];
    __shared__ float Vs[32 * 64];

    const int bh  = blockIdx.y;
    const int qt  = gridDim.x - 1 - blockIdx.x;   // heavy tiles first
    const int q0  = qt * 128;
    const int tid = threadIdx.x;
    const int qi  = q0 + tid;

    const float* Q = g_q + bh * T_ * HD_;
    const float* K = g_k + bh * T_ * HD_;
    const float* V = g_v + bh * T_ * HD_;

    const float scale = 0.125f;
    float q[64];
#pragma unroll
    for (int d = 0; d < 64; d += 4) {
        float4 v4 = *(const float4*)(Q + qi * 64 + d);
        q[d] = v4.x * scale; q[d + 1] = v4.y * scale;
        q[d + 2] = v4.z * scale; q[d + 3] = v4.w * scale;
    }

    float acc[64];
#pragma unroll
    for (int d = 0; d < 64; d++) acc[d] = 0.f;
    float m = -INFINITY, l = 0.f;

    const int kend = q0 + 128;
    for (int k0 = 0; k0 < kend; k0 += 32) {
#pragma unroll
        for (int i = 0; i < 4; i++) {
            int p  = tid + i * 128;
            int r  = p >> 4;
            int c4 = (p & 15) * 4;
            *(float4*)(Ks + r * 64 + c4) = *(const float4*)(K + (k0 + r) * 64 + c4);
            *(float4*)(Vs + r * 64 + c4) = *(const float4*)(V + (k0 + r) * 64 + c4);
        }
        __syncthreads();

        float s[32];
        float tmax = -INFINITY;
#pragma unroll
        for (int jj = 0; jj < 32; jj++) {
            float sum = 0.f;
#pragma unroll
            for (int d = 0; d < 64; d += 4) {
                float4 kv = *(const float4*)(Ks + jj * 64 + d);
                sum += q[d] * kv.x + q[d + 1] * kv.y
                     + q[d + 2] * kv.z + q[d + 3] * kv.w;
            }
            s[jj] = ((k0 + jj) <= qi) ? sum : -INFINITY;
            tmax = fmaxf(tmax, s[jj]);
        }

        float mnew  = fmaxf(m, tmax);
        float alpha = expf(m - mnew);
        m = mnew;
        l *= alpha;
#pragma unroll
        for (int d = 0; d < 64; d++) acc[d] *= alpha;

#pragma unroll
        for (int jj = 0; jj < 32; jj++) {
            float p = expf(s[jj] - mnew);
            l += p;
#pragma unroll
            for (int d = 0; d < 64; d += 4) {
                float4 vv = *(const float4*)(Vs + jj * 64 + d);
                acc[d]     += p * vv.x;
                acc[d + 1] += p * vv.y;
                acc[d + 2] += p * vv.z;
                acc[d + 3] += p * vv.w;
            }
        }
        __syncthreads();
    }

    const int b = bh / NH_, h = bh & (NH_ - 1);
    const float inv_l = 1.f / l;
    const size_t off = ((size_t)(b * T_ + qi) * NH_ + h) * HD_;
#pragma unroll
    for (int d = 0; d < 64; d += 4) {
        float o0 = acc[d] * inv_l, o1 = acc[d + 1] * inv_l;
        float o2 = acc[d + 2] * inv_l, o3 = acc[d + 3] * inv_l;
        __nv_bfloat16 h0 = __float2bfloat16(o0);
        __nv_bfloat16 h1 = __float2bfloat16(o1);
        __nv_bfloat16 h2 = __float2bfloat16(o2);
        __nv_bfloat16 h3 = __float2bfloat16(o3);
        uint2 hi = make_uint2(pk2(h0, h1), pk2(h2, h3));
        uint2 lo = make_uint2(
            pk2(__float2bfloat16(o0 - __bfloat162float(h0)),
                __float2bfloat16(o1 - __bfloat162float(h1))),
            pk2(__float2bfloat16(o2 - __bfloat162float(h2)),
                __float2bfloat16(o3 - __bfloat162float(h3))));
        *reinterpret_cast<uint2*>(g_atthi + off + d) = hi;
        *reinterpret_cast<uint2*>(g_attlo + off + d) = lo;
    }
}

// ============================================================
// launcher
// ============================================================
extern "C" void kernel_launch(void* const* d_in, const int* in_sizes, int n_in,
                              void* d_out, int out_size)
{
    (void)in_sizes; (void)n_in;
    const float* x     = (const float*)d_in[0];
    const float* rnn   = (const float*)d_in[1];
    const float* Wqkv  = (const float*)d_in[2];
    const float* bqkv  = (const float*)d_in[3];
    const float* Wproj = (const float*)d_in[4];
    const float* bproj = (const float*)d_in[5];
    float* out = (float*)d_out;

    cudaFuncSetAttribute(mma_gemm_kernel<3 * C_, 0>,
                         cudaFuncAttributeMaxDynamicSharedMemorySize, SMEM_SZ);
    cudaFuncSetAttribute(mma_gemm_kernel<C_, 1>,
                         cudaFuncAttributeMaxDynamicSharedMemorySize, SMEM_SZ);

    rope_table_kernel<<<(T_ * 32 + 255) / 256, 256>>>();

    xconv_kernel<<<M_ * C_ / 4 / 256, 256>>>(x);
    wconv_kernel<<<dim3(3 * C_ / 32, C_ / 32), dim3(32, 8)>>>(Wqkv, 3 * C_);
    mma_gemm_kernel<3 * C_, 0><<<dim3(24, 64), 256, SMEM_SZ>>>(bqkv, nullptr);

    dim3 rg((B_ * NH_ * T_ * 32 + 255) / 256, 2);
    rope_apply_kernel<<<rg, 256>>>();

    attn_kernel<<<dim3(T_ / 128, B_ * NH_), 128>>>();

    wconv_kernel<<<dim3(C_ / 32, C_ / 32), dim3(32, 8)>>>(Wproj, C_);
    mma_gemm_kernel<C_, 1><<<dim3(8, 64), 256, SMEM_SZ>>>(bproj, out);

    // rnn_state passthrough -> tail of output buffer
    if (out_size >= (int)(M_ * C_ + B_ * C_)) {
        cudaMemcpyAsync(out + (size_t)M_ * C_, rnn,
                        (size_t)B_ * C_ * sizeof(float),
                        cudaMemcpyDeviceToDevice);
    }
}

// round 8
// speedup vs baseline: 3.9180x; 3.0010x over previous
#include <cuda_runtime.h>
#include <cuda_bf16.h>
#include <cuda_fp16.h>
#include <cstdint>
#include <math.h>

#define B_  4
#define T_  2048
#define C_  1024
#define NH_ 16
#define HD_ 64
#define M_  (B_*T_)   // 8192 rows

// ---- scratch (static __device__ arrays: allocation-free) ----
static __device__ float g_q[B_*NH_*T_*HD_];    // [b][h][t][d]
static __device__ float g_k[B_*NH_*T_*HD_];
static __device__ float g_v[B_*NH_*T_*HD_];
static __device__ float g_cos[T_*32];
static __device__ float g_sin[T_*32];
static __device__ __nv_bfloat16 g_ahi[M_*C_];    // x split hi  [m][k]
static __device__ __nv_bfloat16 g_alo[M_*C_];    // x split lo
static __device__ __nv_bfloat16 g_atthi[M_*C_];  // attn out split hi [m][h*64+d]
static __device__ __nv_bfloat16 g_attlo[M_*C_];
static __device__ __nv_bfloat16 g_bhi[3*C_*C_];  // W transposed [N][K] hi
static __device__ __nv_bfloat16 g_blo[3*C_*C_];  // W transposed [N][K] lo

// ============================================================
// helpers (baseline PTX only: works on generic compute_103)
// ============================================================
__device__ __forceinline__ uint32_t smem_u32(const void* p) {
    uint32_t a;
    asm("{ .reg .u64 t; cvta.to.shared.u64 t, %1; cvt.u32.u64 %0, t; }"
        : "=r"(a) : "l"(p));
    return a;
}
__device__ __forceinline__ void cpasync16(uint32_t dst, const void* src) {
    asm volatile("cp.async.ca.shared.global [%0], [%1], 16;"
                 :: "r"(dst), "l"(__cvta_generic_to_global(src)));
}
#define CP_COMMIT() asm volatile("cp.async.commit_group;" ::: "memory")
#define CP_WAIT1()  asm volatile("cp.async.wait_group 1;" ::: "memory")
#define CP_WAIT0()  asm volatile("cp.async.wait_group 0;" ::: "memory")

__device__ __forceinline__ void ldsm4(uint32_t* r, uint32_t addr) {
    asm volatile("ldmatrix.sync.aligned.m8n8.x4.shared.b16 {%0,%1,%2,%3}, [%4];"
                 : "=r"(r[0]), "=r"(r[1]), "=r"(r[2]), "=r"(r[3]) : "r"(addr));
}
__device__ __forceinline__ void ldsm2(uint32_t* r, uint32_t addr) {
    asm volatile("ldmatrix.sync.aligned.m8n8.x2.shared.b16 {%0,%1}, [%2];"
                 : "=r"(r[0]), "=r"(r[1]) : "r"(addr));
}
__device__ __forceinline__ void ldsm2t(uint32_t* r, uint32_t addr) {
    asm volatile("ldmatrix.sync.aligned.m8n8.x2.trans.shared.b16 {%0,%1}, [%2];"
                 : "=r"(r[0]), "=r"(r[1]) : "r"(addr));
}
__device__ __forceinline__ void mma_bf16(float* c, const uint32_t* a, const uint32_t* b) {
    asm volatile("mma.sync.aligned.m16n8k16.row.col.f32.bf16.bf16.f32 "
                 "{%0,%1,%2,%3}, {%4,%5,%6,%7}, {%8,%9}, {%0,%1,%2,%3};"
                 : "+f"(c[0]), "+f"(c[1]), "+f"(c[2]), "+f"(c[3])
                 : "r"(a[0]), "r"(a[1]), "r"(a[2]), "r"(a[3]),
                   "r"(b[0]), "r"(b[1]));
}
__device__ __forceinline__ void mma_f16(float* c, const uint32_t* a, const uint32_t* b) {
    asm volatile("mma.sync.aligned.m16n8k16.row.col.f32.f16.f16.f32 "
                 "{%0,%1,%2,%3}, {%4,%5,%6,%7}, {%8,%9}, {%0,%1,%2,%3};"
                 : "+f"(c[0]), "+f"(c[1]), "+f"(c[2]), "+f"(c[3])
                 : "r"(a[0]), "r"(a[1]), "r"(a[2]), "r"(a[3]),
                   "r"(b[0]), "r"(b[1]));
}
__device__ __forceinline__ uint32_t pk2(__nv_bfloat16 a, __nv_bfloat16 b) {
    __nv_bfloat162 t; t.x = a; t.y = b;
    return *reinterpret_cast<uint32_t*>(&t);
}
__device__ __forceinline__ uint32_t pkh2(float a, float b) {
    __half2 t = __floats2half2_rn(a, b);
    return *reinterpret_cast<uint32_t*>(&t);
}

// ============================================================
// RoPE tables (fp64 once -> fp32 tables)
// ============================================================
__global__ void rope_table_kernel()
{
    int idx = blockIdx.x * blockDim.x + threadIdx.x;
    if (idx >= T_ * 32) return;
    int t = idx >> 5, i = idx & 31;
    double inv = pow(10000.0, -(double)i / 32.0);
    double ang = (double)t * inv;
    g_cos[idx] = (float)cos(ang);
    g_sin[idx] = (float)sin(ang);
}

// ============================================================
// RoPE apply (in-place on g_q / g_k)
// ============================================================
__global__ void rope_apply_kernel()
{
    int idx = blockIdx.x * blockDim.x + threadIdx.x;
    const int total = B_ * NH_ * T_ * 32;
    if (idx >= total) return;
    float* buf = (blockIdx.y == 0) ? g_q : g_k;
    int i   = idx & 31;
    int bht = idx >> 5;
    int t   = bht & (T_ - 1);
    float c = g_cos[t * 32 + i];
    float s = g_sin[t * 32 + i];
    float* base = buf + bht * HD_;
    float x1 = base[i], x2 = base[i + 32];
    base[i]      = x1 * c - x2 * s;
    base[i + 32] = x1 * s + x2 * c;
}

// ============================================================
// x -> bf16 hi/lo split (row-major [m][k])
// ============================================================
__global__ __launch_bounds__(256)
void xconv_kernel(const float* __restrict__ x)
{
    int idx = blockIdx.x * 256 + threadIdx.x;   // over M_*C_/4
    float4 v = reinterpret_cast<const float4*>(x)[idx];
    __nv_bfloat16 h0 = __float2bfloat16(v.x);
    __nv_bfloat16 h1 = __float2bfloat16(v.y);
    __nv_bfloat16 h2 = __float2bfloat16(v.z);
    __nv_bfloat16 h3 = __float2bfloat16(v.w);
    uint2 hi = make_uint2(pk2(h0, h1), pk2(h2, h3));
    uint2 lo = make_uint2(
        pk2(__float2bfloat16(v.x - __bfloat162float(h0)),
            __float2bfloat16(v.y - __bfloat162float(h1))),
        pk2(__float2bfloat16(v.z - __bfloat162float(h2)),
            __float2bfloat16(v.w - __bfloat162float(h3))));
    reinterpret_cast<uint2*>(g_ahi)[idx] = hi;
    reinterpret_cast<uint2*>(g_alo)[idx] = lo;
}

// ============================================================
// W transpose + bf16 hi/lo split: g_b{hi,lo}[n][k] = split(W[k][n])
// ============================================================
__global__ __launch_bounds__(256)
void wconv_kernel(const float* __restrict__ W, int N)
{
    __shared__ float s[32][33];
    const int kb = blockIdx.y * 32, nb = blockIdx.x * 32;
    const int tx = threadIdx.x, ty = threadIdx.y;   // 32 x 8
#pragma unroll
    for (int j = 0; j < 4; j++)
        s[ty * 4 + j][tx] = W[(kb + ty * 4 + j) * N + nb + tx];
    __syncthreads();
#pragma unroll
    for (int j = 0; j < 4; j++) {
        float v = s[tx][ty * 4 + j];
        __nv_bfloat16 h = __float2bfloat16(v);
        float lo = v - __bfloat162float(h);
        int idx = (nb + ty * 4 + j) * C_ + kb + tx;
        g_bhi[idx] = h;
        g_blo[idx] = __float2bfloat16(lo);
    }
}

// ============================================================
// bf16 mma.sync GEMM (passing since R5)
// ============================================================
static constexpr int RSB    = 144;
static constexpr int SA_HI  = 0;
static constexpr int SA_LO  = 18432;
static constexpr int SB_HI  = 36864;
static constexpr int SB_LO  = 55296;
static constexpr int STAGE  = 73728;
static constexpr int SMEM_SZ = 2 * STAGE;   // 147456

template<int N, int MODE>
__global__ __launch_bounds__(256)
void mma_gemm_kernel(const float* __restrict__ bias, float* __restrict__ out)
{
    extern __shared__ __align__(128) char smem[];
    const uint32_t sb = smem_u32(smem);
    const int tid = threadIdx.x, lane = tid & 31, wid = tid >> 5;
    const int wm = wid >> 2, wn = wid & 3;
    const int m0 = blockIdx.y * 128, n0 = blockIdx.x * 128;

    const __nv_bfloat16* Ah = (MODE == 0) ? g_ahi : g_atthi;
    const __nv_bfloat16* Al = (MODE == 0) ? g_alo : g_attlo;

    float acc[4][4][4];
#pragma unroll
    for (int a = 0; a < 4; a++)
#pragma unroll
        for (int b = 0; b < 4; b++)
#pragma unroll
            for (int c = 0; c < 4; c++) acc[a][b][c] = 0.f;

    auto prefetch = [&](int chunk) {
        const int st = chunk & 1;
        const int k0 = chunk * 64;
        const uint32_t sbase = sb + st * STAGE;
#pragma unroll
        for (int i = 0; i < 8; i++) {
            int p = tid + i * 256;
            int sel = p >> 10, q = p & 1023;
            int row = q >> 3, ch = q & 7;
            const __nv_bfloat16* src =
                (sel ? Al : Ah) + (size_t)(m0 + row) * C_ + k0 + ch * 8;
            cpasync16(sbase + (sel ? SA_LO : SA_HI) + row * RSB + ch * 16, src);
        }
#pragma unroll
        for (int i = 0; i < 8; i++) {
            int p = tid + i * 256;
            int sel = p >> 10, q = p & 1023;
            int row = q >> 3, ch = q & 7;
            const __nv_bfloat16* src =
                (sel ? g_blo : g_bhi) + (size_t)(n0 + row) * C_ + k0 + ch * 8;
            cpasync16(sbase + (sel ? SB_LO : SB_HI) + row * RSB + ch * 16, src);
        }
        CP_COMMIT();
    };

    prefetch(0);

    const int a_r = lane & 15;
    const int a_c = (lane >> 4) * 8;
    const int b_r = lane & 7;
    const int b_c = ((lane >> 3) & 1) * 8;

    for (int chunk = 0; chunk < 16; chunk++) {
        if (chunk + 1 < 16) { prefetch(chunk + 1); CP_WAIT1(); }
        else                { CP_WAIT0(); }
        __syncthreads();
        const uint32_t sbase = sb + (chunk & 1) * STAGE;
#pragma unroll
        for (int ks = 0; ks < 4; ks++) {
            uint32_t fAh[4][4], fAl[4][4], fBh[4][2], fBl[4][2];
#pragma unroll
            for (int mi = 0; mi < 4; mi++) {
                uint32_t off = (uint32_t)((wm * 64 + mi * 16 + a_r) * RSB
                                          + (ks * 16 + a_c) * 2);
                ldsm4(fAh[mi], sbase + SA_HI + off);
                ldsm4(fAl[mi], sbase + SA_LO + off);
            }
#pragma unroll
            for (int ni = 0; ni < 4; ni++) {
                uint32_t off = (uint32_t)((wn * 32 + ni * 8 + b_r) * RSB
                                          + (ks * 16 + b_c) * 2);
                ldsm2(fBh[ni], sbase + SB_HI + off);
                ldsm2(fBl[ni], sbase + SB_LO + off);
            }
#pragma unroll
            for (int mi = 0; mi < 4; mi++)
#pragma unroll
                for (int ni = 0; ni < 4; ni++) {
                    mma_bf16(acc[mi][ni], fAh[mi], fBh[ni]);
                    mma_bf16(acc[mi][ni], fAh[mi], fBl[ni]);
                    mma_bf16(acc[mi][ni], fAl[mi], fBh[ni]);
                }
        }
        __syncthreads();
    }

    const int g = lane >> 2, j = lane & 3;
#pragma unroll
    for (int mi = 0; mi < 4; mi++)
#pragma unroll
        for (int ni = 0; ni < 4; ni++)
#pragma unroll
            for (int half = 0; half < 2; half++) {
                int m = m0 + wm * 64 + mi * 16 + g + half * 8;
                int n = n0 + wn * 32 + ni * 8 + 2 * j;
                float v0 = acc[mi][ni][half * 2 + 0] + bias[n];
                float v1 = acc[mi][ni][half * 2 + 1] + bias[n + 1];
                if (MODE == 0) {
                    int sec = n >> 10;
                    int w   = n & 1023;
                    int h = w >> 6, d = w & 63;
                    int bb = m >> 11, t = m & (T_ - 1);
                    float* dst = (sec == 0) ? g_q : (sec == 1) ? g_k : g_v;
                    *(float2*)(dst + (((size_t)(bb * NH_ + h) * T_ + t) * HD_ + d))
                        = make_float2(v0, v1);
                } else {
                    *(float2*)(out + (size_t)m * C_ + n) = make_float2(v0, v1);
                }
            }
}

// ============================================================
// Tensor-core flash attention (fp16 mma, online softmax, exp2)
//   grid (16, 64), 256 thr (8 warps, 16 q-rows each).
//   S = (Qh+Ql)·K   (K fp16 single)
//   O += (Ph+Pl)·Vh + Ph·Vl
//   output: bf16 hi/lo split into g_atthi/lo
// ============================================================
static constexpr int ARS = 144;                 // padded row bytes (64 fp16 + 8)
static constexpr int AQ_HI = 0;                 // Q staging (reused after)
static constexpr int AQ_LO = 18432;
static constexpr int AK    = 0;                 // K tile (after Q consumed)
static constexpr int AV_HI = 9216;
static constexpr int AV_LO = 18432;

__global__ __launch_bounds__(256)
void attn_mma_kernel()
{
    __shared__ __align__(128) char sm[36864];
    const uint32_t sb = smem_u32(sm);
    const int tid = threadIdx.x, lane = tid & 31, w = tid >> 5;
    const int bh = blockIdx.y;
    const int qt = gridDim.x - 1 - blockIdx.x;     // heavy tiles first
    const int q0 = qt * 128;

    const float* Qg = g_q + (size_t)bh * T_ * HD_;
    const float* Kg = g_k + (size_t)bh * T_ * HD_;
    const float* Vg = g_v + (size_t)bh * T_ * HD_;

    const float SCL = 0.125f * 1.4426950408889634f;  // 1/sqrt(64) * log2(e)

    // ---- stage Q (fp16 hi/lo, scaled) ----
#pragma unroll
    for (int i = 0; i < 8; i++) {
        int p = tid + i * 256;          // 2048 float4 slots = 128 rows x 16
        int row = p >> 4, c4 = (p & 15) * 4;
        float4 v = *(const float4*)(Qg + (size_t)(q0 + row) * HD_ + c4);
        v.x *= SCL; v.y *= SCL; v.z *= SCL; v.w *= SCL;
        __half2 h01 = __floats2half2_rn(v.x, v.y);
        __half2 h23 = __floats2half2_rn(v.z, v.w);
        float2 f01 = __half22float2(h01);
        float2 f23 = __half22float2(h23);
        uint32_t l01 = pkh2(v.x - f01.x, v.y - f01.y);
        uint32_t l23 = pkh2(v.z - f23.x, v.w - f23.y);
        uint32_t off = row * ARS + c4 * 2;
        *(uint2*)(sm + AQ_HI + off) = make_uint2(*(uint32_t*)&h01, *(uint32_t*)&h23);
        *(uint2*)(sm + AQ_LO + off) = make_uint2(l01, l23);
    }
    __syncthreads();

    // ---- Q fragments into registers ----
    const int a_r = lane & 15, a_c = (lane >> 4) * 8;
    uint32_t aQh[4][4], aQl[4][4];
#pragma unroll
    for (int ks = 0; ks < 4; ks++) {
        uint32_t off = (uint32_t)((w * 16 + a_r) * ARS + (ks * 16 + a_c) * 2);
        ldsm4(aQh[ks], sb + AQ_HI + off);
        ldsm4(aQl[ks], sb + AQ_LO + off);
    }
    __syncthreads();   // Q smem region now free for K/V

    float o[8][4];
#pragma unroll
    for (int n = 0; n < 8; n++)
#pragma unroll
        for (int c = 0; c < 4; c++) o[n][c] = 0.f;
    float mrow0 = -INFINITY, mrow1 = -INFINITY;
    float lrow0 = 0.f, lrow1 = 0.f;

    const int g = lane >> 2, j = lane & 3;
    const int b_r = lane & 7, b_c = ((lane >> 3) & 1) * 8;
    const int qw0 = q0 + w * 16;                  // warp's first query row
    const int ntiles = qt * 2 + 2;

    for (int kt = 0; kt < ntiles; kt++) {
        const int k0 = kt * 64;
        // ---- fill K (hi), V (hi/lo) tiles ----
#pragma unroll
        for (int i = 0; i < 4; i++) {
            int p = tid + i * 256;       // 1024 float4 slots = 64 rows x 16
            int row = p >> 4, c4 = (p & 15) * 4;
            uint32_t off = row * ARS + c4 * 2;
            float4 kv = *(const float4*)(Kg + (size_t)(k0 + row) * HD_ + c4);
            *(uint2*)(sm + AK + off) =
                make_uint2(pkh2(kv.x, kv.y), pkh2(kv.z, kv.w));
            float4 vv = *(const float4*)(Vg + (size_t)(k0 + row) * HD_ + c4);
            __half2 vh01 = __floats2half2_rn(vv.x, vv.y);
            __half2 vh23 = __floats2half2_rn(vv.z, vv.w);
            float2 f01 = __half22float2(vh01);
            float2 f23 = __half22float2(vh23);
            *(uint2*)(sm + AV_HI + off) =
                make_uint2(*(uint32_t*)&vh01, *(uint32_t*)&vh23);
            *(uint2*)(sm + AV_LO + off) =
                make_uint2(pkh2(vv.x - f01.x, vv.y - f01.y),
                           pkh2(vv.z - f23.x, vv.w - f23.y));
        }
        __syncthreads();

        if (k0 <= qw0 + 15) {   // warp has at least one unmasked row
            // ---- S = Q . K^T ----
            float c[8][4];
#pragma unroll
            for (int n = 0; n < 8; n++)
#pragma unroll
                for (int cc = 0; cc < 4; cc++) c[n][cc] = 0.f;
#pragma unroll
            for (int ks = 0; ks < 4; ks++) {
#pragma unroll
                for (int nn = 0; nn < 8; nn++) {
                    uint32_t bK[2];
                    ldsm2(bK, sb + AK + (uint32_t)((nn * 8 + b_r) * ARS
                                                   + (ks * 16 + b_c) * 2));
                    mma_f16(c[nn], aQh[ks], bK);
                    mma_f16(c[nn], aQl[ks], bK);
                }
            }
            // ---- causal mask ----
            if (k0 + 63 > qw0) {
                const int r0 = qw0 + g, r1 = qw0 + 8 + g;
#pragma unroll
                for (int nn = 0; nn < 8; nn++) {
                    int key = k0 + nn * 8 + 2 * j;
                    if (key     > r0) c[nn][0] = -INFINITY;
                    if (key + 1 > r0) c[nn][1] = -INFINITY;
                    if (key     > r1) c[nn][2] = -INFINITY;
                    if (key + 1 > r1) c[nn][3] = -INFINITY;
                }
            }
            // ---- row max (reduce over j lanes) ----
            float t0 = -INFINITY, t1 = -INFINITY;
#pragma unroll
            for (int nn = 0; nn < 8; nn++) {
                t0 = fmaxf(t0, fmaxf(c[nn][0], c[nn][1]));
                t1 = fmaxf(t1, fmaxf(c[nn][2], c[nn][3]));
            }
            t0 = fmaxf(t0, __shfl_xor_sync(0xffffffffu, t0, 1));
            t0 = fmaxf(t0, __shfl_xor_sync(0xffffffffu, t0, 2));
            t1 = fmaxf(t1, __shfl_xor_sync(0xffffffffu, t1, 1));
            t1 = fmaxf(t1, __shfl_xor_sync(0xffffffffu, t1, 2));
            float mn0 = fmaxf(mrow0, t0), mn1 = fmaxf(mrow1, t1);
            float al0 = exp2f(mrow0 - mn0), al1 = exp2f(mrow1 - mn1);
            mrow0 = mn0; mrow1 = mn1;
            lrow0 *= al0; lrow1 *= al1;
#pragma unroll
            for (int nn = 0; nn < 8; nn++) {
                o[nn][0] *= al0; o[nn][1] *= al0;
                o[nn][2] *= al1; o[nn][3] *= al1;
            }
            // ---- p = exp2(s-m), split fp16 hi/lo, build A frags ----
            uint32_t aPh[4][4], aPl[4][4];
#pragma unroll
            for (int nn = 0; nn < 8; nn++) {
                float p0 = exp2f(c[nn][0] - mn0);
                float p1 = exp2f(c[nn][1] - mn0);
                float p2 = exp2f(c[nn][2] - mn1);
                float p3 = exp2f(c[nn][3] - mn1);
                lrow0 += p0 + p1;
                lrow1 += p2 + p3;
                __half2 h01 = __floats2half2_rn(p0, p1);
                __half2 h23 = __floats2half2_rn(p2, p3);
                float2 f01 = __half22float2(h01);
                float2 f23 = __half22float2(h23);
                int ks = nn >> 1, sl = (nn & 1) * 2;
                aPh[ks][sl + 0] = *(uint32_t*)&h01;
                aPh[ks][sl + 1] = *(uint32_t*)&h23;
                aPl[ks][sl + 0] = pkh2(p0 - f01.x, p1 - f01.y);
                aPl[ks][sl + 1] = pkh2(p2 - f23.x, p3 - f23.y);
            }
            // ---- O += P . V ----
#pragma unroll
            for (int ks = 0; ks < 4; ks++) {
                uint32_t rbase = sb + (uint32_t)((ks * 16 + (lane & 15)) * ARS);
#pragma unroll
                for (int nn = 0; nn < 8; nn++) {
                    uint32_t bVh[2], bVl[2];
                    ldsm2t(bVh, rbase + AV_HI + nn * 16);
                    ldsm2t(bVl, rbase + AV_LO + nn * 16);
                    mma_f16(o[nn], aPh[ks], bVh);
                    mma_f16(o[nn], aPl[ks], bVh);
                    mma_f16(o[nn], aPh[ks], bVl);
                }
            }
        }
        __syncthreads();
    }

    // ---- finalize: reduce l over j lanes, normalize, write split ----
    lrow0 += __shfl_xor_sync(0xffffffffu, lrow0, 1);
    lrow0 += __shfl_xor_sync(0xffffffffu, lrow0, 2);
    lrow1 += __shfl_xor_sync(0xffffffffu, lrow1, 1);
    lrow1 += __shfl_xor_sync(0xffffffffu, lrow1, 2);
    float inv0 = 1.f / lrow0, inv1 = 1.f / lrow1;

    const int b = bh >> 4, h = bh & 15;
    const int m0r = q0 + w * 16 + g, m1r = m0r + 8;
    const size_t base0 = (size_t)(b * T_ + m0r) * C_ + h * 64;
    const size_t base1 = (size_t)(b * T_ + m1r) * C_ + h * 64;
#pragma unroll
    for (int nn = 0; nn < 8; nn++) {
        int d = nn * 8 + 2 * j;
        float v0 = o[nn][0] * inv0, v1 = o[nn][1] * inv0;
        float v2 = o[nn][2] * inv1, v3 = o[nn][3] * inv1;
        __nv_bfloat16 h0 = __float2bfloat16(v0), h1 = __float2bfloat16(v1);
        __nv_bfloat16 h2 = __float2bfloat16(v2), h3 = __float2bfloat16(v3);
        *(uint32_t*)(g_atthi + base0 + d) = pk2(h0, h1);
        *(uint32_t*)(g_attlo + base0 + d) =
            pk2(__float2bfloat16(v0 - __bfloat162float(h0)),
                __float2bfloat16(v1 - __bfloat162float(h1)));
        *(uint32_t*)(g_atthi + base1 + d) = pk2(h2, h3);
        *(uint32_t*)(g_attlo + base1 + d) =
            pk2(__float2bfloat16(v2 - __bfloat162float(h2)),
                __float2bfloat16(v3 - __bfloat162float(h3)));
    }
}

// ============================================================
// launcher
// ============================================================
extern "C" void kernel_launch(void* const* d_in, const int* in_sizes, int n_in,
                              void* d_out, int out_size)
{
    (void)in_sizes; (void)n_in;
    const float* x     = (const float*)d_in[0];
    const float* rnn   = (const float*)d_in[1];
    const float* Wqkv  = (const float*)d_in[2];
    const float* bqkv  = (const float*)d_in[3];
    const float* Wproj = (const float*)d_in[4];
    const float* bproj = (const float*)d_in[5];
    float* out = (float*)d_out;

    cudaFuncSetAttribute(mma_gemm_kernel<3 * C_, 0>,
                         cudaFuncAttributeMaxDynamicSharedMemorySize, SMEM_SZ);
    cudaFuncSetAttribute(mma_gemm_kernel<C_, 1>,
                         cudaFuncAttributeMaxDynamicSharedMemorySize, SMEM_SZ);

    rope_table_kernel<<<(T_ * 32 + 255) / 256, 256>>>();

    xconv_kernel<<<M_ * C_ / 4 / 256, 256>>>(x);
    wconv_kernel<<<dim3(3 * C_ / 32, C_ / 32), dim3(32, 8)>>>(Wqkv, 3 * C_);
    mma_gemm_kernel<3 * C_, 0><<<dim3(24, 64), 256, SMEM_SZ>>>(bqkv, nullptr);

    dim3 rg((B_ * NH_ * T_ * 32 + 255) / 256, 2);
    rope_apply_kernel<<<rg, 256>>>();

    attn_mma_kernel<<<dim3(16, 64), 256>>>();

    wconv_kernel<<<dim3(C_ / 32, C_ / 32), dim3(32, 8)>>>(Wproj, C_);
    mma_gemm_kernel<C_, 1><<<dim3(8, 64), 256, SMEM_SZ>>>(bproj, out);

    if (out_size >= (int)(M_ * C_ + B_ * C_)) {
        cudaMemcpyAsync(out + (size_t)M_ * C_, rnn,
                        (size_t)B_ * C_ * sizeof(float),
                        cudaMemcpyDeviceToDevice);
    }
}